// round 3
// baseline (speedup 1.0000x reference)
#include <cuda_runtime.h>
#include <math.h>

#define N_NODES 100000
#define N_EDGES 1600000
#define IN_F 128
#define OUT_F 32
#define NEG_SLOPE 0.2f

// Scratch (device globals: no allocation allowed)
__device__ float g_z[(size_t)N_NODES * OUT_F];
__device__ float g_el[N_NODES];
__device__ float g_er[N_NODES];
__device__ float g_denom[N_NODES];

// ---------------------------------------------------------------------------
// K1: z = h @ W^T, el = z@a_l, er = z@a_r. Also zeros g_denom and d_out.
// 8 warps/block, 1 row/warp. Grid 12500 -> 3.2M threads == out elements.
// ---------------------------------------------------------------------------
__global__ __launch_bounds__(256) void k_gemm(
    const float* __restrict__ h, const float* __restrict__ W,
    const float* __restrict__ a, float* __restrict__ out)
{
    __shared__ float Wt[IN_F * OUT_F];   // Wt[k*32 + j] = W[j*128 + k]
    __shared__ float hrow[8][IN_F];

    int tid = threadIdx.x;

    // zero pass: denom + out (grid covers exactly 3.2M threads)
    size_t gt = (size_t)blockIdx.x * 256 + tid;
    if (gt < N_NODES) g_denom[gt] = 0.0f;
    out[gt] = 0.0f;   // gt < 3,200,000 == out_size exactly

    // stage W transposed into shared
    for (int i = tid; i < IN_F * OUT_F; i += 256) {
        int j = i / IN_F;
        int k = i - j * IN_F;
        Wt[k * OUT_F + j] = W[i];
    }

    int w = tid >> 5;
    int lane = tid & 31;
    int row = blockIdx.x * 8 + w;

    // stage h row (128 floats) via float4
    float4 hv = ((const float4*)(h + (size_t)row * IN_F))[lane];
    ((float4*)hrow[w])[lane] = hv;
    __syncthreads();

    float acc = 0.0f;
    #pragma unroll
    for (int k = 0; k < IN_F; k++)
        acc = fmaf(hrow[w][k], Wt[k * OUT_F + lane], acc);

    g_z[(size_t)row * OUT_F + lane] = acc;

    float al = a[lane];
    float ar = a[lane + OUT_F];
    float el = acc * al;
    float er = acc * ar;
    #pragma unroll
    for (int o = 16; o > 0; o >>= 1) {
        el += __shfl_xor_sync(0xffffffffu, el, o);
        er += __shfl_xor_sync(0xffffffffu, er, o);
    }
    if (lane == 0) {
        g_el[row] = el;
        g_er[row] = er;
    }
}

// ---------------------------------------------------------------------------
// K2: per-edge ex = exp(leaky_relu(el[src]+er[dst])); denom[dst] += ex
// (max-shift dropped: mathematically cancels in alpha, values are small)
// ---------------------------------------------------------------------------
__global__ __launch_bounds__(256) void k_denom(
    const int* __restrict__ src, const int* __restrict__ dst)
{
    int e = blockIdx.x * 256 + threadIdx.x;
    if (e >= N_EDGES) return;
    int s = src[e];
    int d = dst[e];
    float v = g_el[s] + g_er[d];
    v = (v > 0.0f) ? v : NEG_SLOPE * v;
    float ex = __expf(v);
    atomicAdd(&g_denom[d], ex);
}

// ---------------------------------------------------------------------------
// K3: per-edge out[dst] += (ex/denom[dst]) * z[src], 8 threads/edge,
// each thread does one float4 vector reduction (red.global.add.v4.f32).
// ---------------------------------------------------------------------------
__global__ __launch_bounds__(256) void k_agg(
    const int* __restrict__ src, const int* __restrict__ dst,
    float* __restrict__ out)
{
    int t = blockIdx.x * 256 + threadIdx.x;
    int e = t >> 3;
    if (e >= N_EDGES) return;
    int seg = t & 7;

    int s = src[e];
    int d = dst[e];
    float v = g_el[s] + g_er[d];
    v = (v > 0.0f) ? v : NEG_SLOPE * v;
    float ex = __expf(v);
    float alpha = ex / fmaxf(g_denom[d], 1e-16f);

    float4 zv = ((const float4*)(g_z + (size_t)s * OUT_F))[seg];
    float mx = zv.x * alpha;
    float my = zv.y * alpha;
    float mz = zv.z * alpha;
    float mw = zv.w * alpha;

    float* p = out + (size_t)d * OUT_F + seg * 4;
    asm volatile("red.global.add.v4.f32 [%0], {%1, %2, %3, %4};"
                 :: "l"(p), "f"(mx), "f"(my), "f"(mz), "f"(mw)
                 : "memory");
}

// ---------------------------------------------------------------------------
extern "C" void kernel_launch(void* const* d_in, const int* in_sizes, int n_in,
                              void* d_out, int out_size)
{
    const float* h   = (const float*)d_in[0];
    const float* W   = (const float*)d_in[1];
    const float* a   = (const float*)d_in[2];
    const int*   src = (const int*)d_in[3];
    const int*   dst = (const int*)d_in[4];
    float* out = (float*)d_out;

    (void)in_sizes; (void)n_in; (void)out_size;

    k_gemm<<<N_NODES / 8, 256>>>(h, W, a, out);                       // 12500 blocks
    k_denom<<<(N_EDGES + 255) / 256, 256>>>(src, dst);                // 6250 blocks
    k_agg<<<((N_EDGES * 8) + 255) / 256, 256>>>(src, dst, out);       // 50000 blocks
}

// round 4
// speedup vs baseline: 2.3619x; 2.3619x over previous
#include <cuda_runtime.h>
#include <math.h>

#define N_NODES 100000
#define N_EDGES 1600000
#define IN_F 128
#define OUT_F 32
#define NEG_SLOPE 0.2f

#define ROWS_PB 64              // rows per block in K1
#define K1_BLOCKS ((N_NODES + ROWS_PB - 1) / ROWS_PB)   // 1563

// Scratch (device globals: no allocation allowed)
__device__ float g_z[(size_t)N_NODES * OUT_F];
__device__ float g_el[N_NODES];
__device__ float g_er[N_NODES];
__device__ float g_denom[N_NODES];

// ---------------------------------------------------------------------------
// K1: z = h @ W^T, el = z@a_l, er = z@a_r. Also zeros g_denom and d_out.
// 256 threads, 64 rows/block. Thread computes 8 rows x 1 col, k-unrolled x4.
// FMA:LDS ~2.7 (was 0.5) -> FMA-pipe bound instead of LDS-bound.
// ---------------------------------------------------------------------------
__global__ __launch_bounds__(256) void k_gemm(
    const float* __restrict__ h, const float* __restrict__ W,
    const float* __restrict__ a, float* __restrict__ out)
{
    __shared__ float hs[ROWS_PB][IN_F];     // 32 KB
    __shared__ float Wt[IN_F][OUT_F];       // 16 KB, Wt[k][j] = W[j][k]

    const int tid  = threadIdx.x;
    const int col  = tid & 31;
    const int rgrp = tid >> 5;              // 0..7, 8 rows each
    const int row0 = blockIdx.x * ROWS_PB;

    // --- zero pass: out (3.2M) + denom (100k), grid-stride ---
    {
        const int stride = K1_BLOCKS * 256;
        for (int i = blockIdx.x * 256 + tid; i < N_NODES * OUT_F; i += stride)
            out[i] = 0.0f;
        int di = blockIdx.x * 256 + tid;
        if (di < N_NODES) g_denom[di] = 0.0f;
    }

    // --- stage W transposed ---
    for (int i = tid; i < IN_F * OUT_F; i += 256) {
        int j = i >> 7;             // i / 128
        int k = i & 127;
        Wt[k][j] = W[i];
    }

    // --- stage h tile (64 rows x 128) as float4, coalesced ---
    {
        const float4* h4 = (const float4*)h;
        float4* hs4 = (float4*)hs;
        #pragma unroll
        for (int i = 0; i < (ROWS_PB * IN_F / 4) / 256; i++) {   // 8 iters
            int idx = i * 256 + tid;                 // over [64][32] float4
            int r = idx >> 5;
            float4 v = make_float4(0.f, 0.f, 0.f, 0.f);
            if (row0 + r < N_NODES)
                v = h4[(size_t)(row0 + r) * (IN_F / 4) + (idx & 31)];
            hs4[idx] = v;
        }
    }
    __syncthreads();

    // --- main loop: 8 rows x 1 col per thread ---
    float acc[8] = {0.f, 0.f, 0.f, 0.f, 0.f, 0.f, 0.f, 0.f};
    const int rbase = rgrp * 8;

    #pragma unroll 8
    for (int k4 = 0; k4 < IN_F; k4 += 4) {
        float w0 = Wt[k4 + 0][col];
        float w1 = Wt[k4 + 1][col];
        float w2 = Wt[k4 + 2][col];
        float w3 = Wt[k4 + 3][col];
        #pragma unroll
        for (int i = 0; i < 8; i++) {
            float4 hv = *(const float4*)&hs[rbase + i][k4];
            acc[i] = fmaf(hv.x, w0, acc[i]);
            acc[i] = fmaf(hv.y, w1, acc[i]);
            acc[i] = fmaf(hv.z, w2, acc[i]);
            acc[i] = fmaf(hv.w, w3, acc[i]);
        }
    }

    // --- epilogue: store z, reduce el/er per row ---
    const float al = a[col];
    const float ar = a[col + OUT_F];

    #pragma unroll
    for (int i = 0; i < 8; i++) {
        int row = row0 + rbase + i;
        bool ok = (row < N_NODES);
        if (ok) g_z[(size_t)row * OUT_F + col] = acc[i];

        float el = acc[i] * al;
        float er = acc[i] * ar;
        #pragma unroll
        for (int o = 16; o > 0; o >>= 1) {
            el += __shfl_xor_sync(0xffffffffu, el, o);
            er += __shfl_xor_sync(0xffffffffu, er, o);
        }
        if (ok && col == 0) {
            g_el[row] = el;
            g_er[row] = er;
        }
    }
}

// ---------------------------------------------------------------------------
// K2: per-edge ex = exp(leaky_relu(el[src]+er[dst])); denom[dst] += ex
// (max-shift dropped: mathematically cancels in alpha, values are small)
// ---------------------------------------------------------------------------
__global__ __launch_bounds__(256) void k_denom(
    const int* __restrict__ src, const int* __restrict__ dst)
{
    int e = blockIdx.x * 256 + threadIdx.x;
    if (e >= N_EDGES) return;
    int s = src[e];
    int d = dst[e];
    float v = g_el[s] + g_er[d];
    v = (v > 0.0f) ? v : NEG_SLOPE * v;
    float ex = __expf(v);
    atomicAdd(&g_denom[d], ex);
}

// ---------------------------------------------------------------------------
// K3: per-edge out[dst] += (ex/denom[dst]) * z[src], 8 threads/edge,
// each thread does one float4 vector reduction (red.global.add.v4.f32).
// ---------------------------------------------------------------------------
__global__ __launch_bounds__(256) void k_agg(
    const int* __restrict__ src, const int* __restrict__ dst,
    float* __restrict__ out)
{
    int t = blockIdx.x * 256 + threadIdx.x;
    int e = t >> 3;
    if (e >= N_EDGES) return;
    int seg = t & 7;

    int s = src[e];
    int d = dst[e];
    float v = g_el[s] + g_er[d];
    v = (v > 0.0f) ? v : NEG_SLOPE * v;
    float ex = __expf(v);
    float alpha = ex / fmaxf(g_denom[d], 1e-16f);

    float4 zv = ((const float4*)(g_z + (size_t)s * OUT_F))[seg];
    float mx = zv.x * alpha;
    float my = zv.y * alpha;
    float mz = zv.z * alpha;
    float mw = zv.w * alpha;

    float* p = out + (size_t)d * OUT_F + seg * 4;
    asm volatile("red.global.add.v4.f32 [%0], {%1, %2, %3, %4};"
                 :: "l"(p), "f"(mx), "f"(my), "f"(mz), "f"(mw)
                 : "memory");
}

// ---------------------------------------------------------------------------
extern "C" void kernel_launch(void* const* d_in, const int* in_sizes, int n_in,
                              void* d_out, int out_size)
{
    const float* h   = (const float*)d_in[0];
    const float* W   = (const float*)d_in[1];
    const float* a   = (const float*)d_in[2];
    const int*   src = (const int*)d_in[3];
    const int*   dst = (const int*)d_in[4];
    float* out = (float*)d_out;

    (void)in_sizes; (void)n_in; (void)out_size;

    k_gemm<<<K1_BLOCKS, 256>>>(h, W, a, out);                         // 1563 blocks
    k_denom<<<(N_EDGES + 255) / 256, 256>>>(src, dst);                // 6250 blocks
    k_agg<<<((N_EDGES * 8) + 255) / 256, 256>>>(src, dst, out);       // 50000 blocks
}

// round 5
// speedup vs baseline: 2.6246x; 1.1112x over previous
#include <cuda_runtime.h>
#include <math.h>

#define N_NODES 100000
#define N_EDGES 1600000
#define IN_F 128
#define OUT_F 32
#define NEG_SLOPE 0.2f

#define ROWS_PB 256                                  // rows per block in K1
#define K1_BLOCKS ((N_NODES + ROWS_PB - 1) / ROWS_PB)   // 391

// Scratch (device globals: no allocation allowed)
__device__ float g_z[(size_t)N_NODES * OUT_F];
__device__ float g_el[N_NODES];
__device__ float g_er[N_NODES];
__device__ float g_denom[N_NODES];
__device__ float g_ex[N_EDGES];

// ---------------------------------------------------------------------------
// K1: z = h @ W^T, el = z@a_l, er = z@a_r. Also zeros g_denom and d_out.
// 256 threads; thread = (row_grp = tid>>3) x (col_grp = tid&7).
// Tile per thread: 8 rows x 4 cols (32 acc). h read directly from global
// (each row consumed by exactly one 8-lane group -> broadcast LDG.128,
//  shared staging would buy nothing). W transposed in 16KB shared.
// LD:FMA ~ 1:10.7 -> FMA-pipe bound (floor ~24us chip-wide).
// ---------------------------------------------------------------------------
__global__ __launch_bounds__(256) void k_gemm(
    const float* __restrict__ h, const float* __restrict__ W,
    const float* __restrict__ a, float* __restrict__ out)
{
    __shared__ float Wt[IN_F][OUT_F];       // 16 KB, Wt[k][j] = W[j][k]

    const int tid      = threadIdx.x;
    const int col0     = (tid & 7) * 4;     // 4 cols per thread
    const int row_grp  = tid >> 3;          // 32 groups x 8 rows
    const int row_base = blockIdx.x * ROWS_PB + row_grp * 8;

    // --- zero pass: out (3.2M floats) + denom, grid-stride float4 ---
    {
        float4* out4 = (float4*)out;
        const int n4 = N_NODES * OUT_F / 4;             // 800000
        const int stride = K1_BLOCKS * 256;
        for (int i = blockIdx.x * 256 + tid; i < n4; i += stride)
            out4[i] = make_float4(0.f, 0.f, 0.f, 0.f);
        int di = blockIdx.x * 256 + tid;
        if (di < N_NODES) g_denom[di] = 0.0f;
    }

    // --- stage W transposed ---
    for (int i = tid; i < IN_F * OUT_F; i += 256) {
        int j = i >> 7;             // i / 128
        int k = i & 127;
        Wt[k][j] = W[i];
    }
    __syncthreads();

    // row indices (clamped for tail block; stores predicated)
    int rows[8];
    #pragma unroll
    for (int i = 0; i < 8; i++) {
        int r = row_base + i;
        rows[i] = (r < N_NODES) ? r : (N_NODES - 1);
    }

    const float4* h4 = (const float4*)h;    // row stride = 32 float4

    float4 acc[8];
    #pragma unroll
    for (int i = 0; i < 8; i++) acc[i] = make_float4(0.f, 0.f, 0.f, 0.f);

    #pragma unroll 4
    for (int k4 = 0; k4 < IN_F / 4; k4++) {
        // W slice: 4 k-values x 4 cols
        float4 wv0 = *(const float4*)&Wt[k4 * 4 + 0][col0];
        float4 wv1 = *(const float4*)&Wt[k4 * 4 + 1][col0];
        float4 wv2 = *(const float4*)&Wt[k4 * 4 + 2][col0];
        float4 wv3 = *(const float4*)&Wt[k4 * 4 + 3][col0];

        #pragma unroll
        for (int i = 0; i < 8; i++) {
            float4 hv = h4[(size_t)rows[i] * (IN_F / 4) + k4];
            acc[i].x = fmaf(hv.x, wv0.x, acc[i].x);
            acc[i].y = fmaf(hv.x, wv0.y, acc[i].y);
            acc[i].z = fmaf(hv.x, wv0.z, acc[i].z);
            acc[i].w = fmaf(hv.x, wv0.w, acc[i].w);
            acc[i].x = fmaf(hv.y, wv1.x, acc[i].x);
            acc[i].y = fmaf(hv.y, wv1.y, acc[i].y);
            acc[i].z = fmaf(hv.y, wv1.z, acc[i].z);
            acc[i].w = fmaf(hv.y, wv1.w, acc[i].w);
            acc[i].x = fmaf(hv.z, wv2.x, acc[i].x);
            acc[i].y = fmaf(hv.z, wv2.y, acc[i].y);
            acc[i].z = fmaf(hv.z, wv2.z, acc[i].z);
            acc[i].w = fmaf(hv.z, wv2.w, acc[i].w);
            acc[i].x = fmaf(hv.w, wv3.x, acc[i].x);
            acc[i].y = fmaf(hv.w, wv3.y, acc[i].y);
            acc[i].z = fmaf(hv.w, wv3.z, acc[i].z);
            acc[i].w = fmaf(hv.w, wv3.w, acc[i].w);
        }
    }

    // --- epilogue: store z (float4, coalesced 128B per row), el/er ---
    const float4 al4 = *(const float4*)&a[col0];
    const float4 ar4 = *(const float4*)&a[OUT_F + col0];

    #pragma unroll
    for (int i = 0; i < 8; i++) {
        int r = row_base + i;
        bool ok = (r < N_NODES);
        if (ok)
            *(float4*)&g_z[(size_t)r * OUT_F + col0] = acc[i];

        // partial el/er over this thread's 4 cols, reduce across 8-lane group
        float pel = acc[i].x * al4.x + acc[i].y * al4.y
                  + acc[i].z * al4.z + acc[i].w * al4.w;
        float per = acc[i].x * ar4.x + acc[i].y * ar4.y
                  + acc[i].z * ar4.z + acc[i].w * ar4.w;
        #pragma unroll
        for (int o = 4; o > 0; o >>= 1) {
            pel += __shfl_xor_sync(0xffffffffu, pel, o);
            per += __shfl_xor_sync(0xffffffffu, per, o);
        }
        if (ok && (tid & 7) == 0) {
            g_el[r] = pel;
            g_er[r] = per;
        }
    }
}

// ---------------------------------------------------------------------------
// K2: ex[e] = exp(leaky_relu(el[src]+er[dst])); denom[dst] += ex; store ex.
// (max-shift dropped: mathematically cancels in alpha, values are small)
// ---------------------------------------------------------------------------
__global__ __launch_bounds__(256) void k_denom(
    const int* __restrict__ src, const int* __restrict__ dst)
{
    int e = blockIdx.x * 256 + threadIdx.x;
    if (e >= N_EDGES) return;
    int s = src[e];
    int d = dst[e];
    float v = g_el[s] + g_er[d];
    v = (v > 0.0f) ? v : NEG_SLOPE * v;
    float ex = __expf(v);
    g_ex[e] = ex;
    atomicAdd(&g_denom[d], ex);
}

// ---------------------------------------------------------------------------
// K3: out[dst] += (ex[e]/denom[dst]) * z[src], 8 threads/edge.
// Only lane seg==0 does the scalar loads + divide; alpha/s/d broadcast via
// shfl. z gather is a single coalesced 128B request per edge; accumulation
// via red.global.add.v4.f32.
// Grid covers exactly N_EDGES*8 threads (no tail).
// ---------------------------------------------------------------------------
__global__ __launch_bounds__(256) void k_agg(
    const int* __restrict__ src, const int* __restrict__ dst,
    float* __restrict__ out)
{
    int t = blockIdx.x * 256 + threadIdx.x;
    int e = t >> 3;
    int seg = t & 7;
    int base = threadIdx.x & 24;    // base lane (within warp) of 8-lane group

    float alpha = 0.0f;
    int s = 0, d = 0;
    if (seg == 0) {
        d = dst[e];
        s = src[e];
        alpha = g_ex[e] / fmaxf(g_denom[d], 1e-16f);
    }
    alpha = __shfl_sync(0xffffffffu, alpha, base);
    s     = __shfl_sync(0xffffffffu, s, base);
    d     = __shfl_sync(0xffffffffu, d, base);

    float4 zv = ((const float4*)(g_z + (size_t)s * OUT_F))[seg];
    float mx = zv.x * alpha;
    float my = zv.y * alpha;
    float mz = zv.z * alpha;
    float mw = zv.w * alpha;

    float* p = out + (size_t)d * OUT_F + seg * 4;
    asm volatile("red.global.add.v4.f32 [%0], {%1, %2, %3, %4};"
                 :: "l"(p), "f"(mx), "f"(my), "f"(mz), "f"(mw)
                 : "memory");
}

// ---------------------------------------------------------------------------
extern "C" void kernel_launch(void* const* d_in, const int* in_sizes, int n_in,
                              void* d_out, int out_size)
{
    const float* h   = (const float*)d_in[0];
    const float* W   = (const float*)d_in[1];
    const float* a   = (const float*)d_in[2];
    const int*   src = (const int*)d_in[3];
    const int*   dst = (const int*)d_in[4];
    float* out = (float*)d_out;

    (void)in_sizes; (void)n_in; (void)out_size;

    k_gemm<<<K1_BLOCKS, 256>>>(h, W, a, out);                 // 391 blocks
    k_denom<<<(N_EDGES + 255) / 256, 256>>>(src, dst);        // 6250 blocks
    k_agg<<<(N_EDGES * 8) / 256, 256>>>(src, dst, out);       // 50000 blocks
}

// round 6
// speedup vs baseline: 2.7550x; 1.0497x over previous
#include <cuda_runtime.h>
#include <math.h>

#define N_NODES 100000
#define N_EDGES 1600000
#define IN_F 128
#define OUT_F 32
#define NEG_SLOPE 0.2f

#define ROWS_PB 128
#define K1_BLOCKS ((N_NODES + ROWS_PB - 1) / ROWS_PB)   // 782

#define SCAN_CHUNK 1024
#define SCAN_BLOCKS ((N_NODES + SCAN_CHUNK - 1) / SCAN_CHUNK)  // 98

// Scratch (device globals: no allocation allowed)
__device__ float g_z[(size_t)N_NODES * OUT_F];
__device__ float g_el[N_NODES];
__device__ float g_er[N_NODES];
__device__ int   g_cnt[N_NODES];      // per-node edge count
__device__ int   g_off[N_NODES];      // exclusive prefix (CSR row starts)
__device__ int   g_cur[N_NODES];      // scatter cursors
__device__ int   g_bsum[SCAN_BLOCKS]; // scan block sums
__device__ int2  g_srcex[N_EDGES];    // (src, ex-as-bits) sorted by dst

// ---------------------------------------------------------------------------
// K1: z = h @ W^T, el/er row dots. Also zeros g_cnt / g_cur.
// 256 threads; tile 4 rows x 4 cols per thread; h direct from global
// (each row consumed by one 8-lane group -> broadcast LDG.128).
// launch_bounds(256,3): regs<=85 -> ~37% occ -> enough MLP to stream h.
// ---------------------------------------------------------------------------
__global__ __launch_bounds__(256, 3) void k_gemm(
    const float* __restrict__ h, const float* __restrict__ W,
    const float* __restrict__ a)
{
    __shared__ float Wt[IN_F][OUT_F];       // 16 KB, Wt[k][j] = W[j][k]

    const int tid      = threadIdx.x;
    const int col0     = (tid & 7) * 4;     // 4 cols per thread
    const int row_grp  = tid >> 3;          // 32 groups x 4 rows = 128 rows
    const int row_base = blockIdx.x * ROWS_PB + row_grp * 4;

    // zero cnt + cur (grid 200k threads covers 100k nodes)
    {
        int i = blockIdx.x * 256 + tid;
        if (i < N_NODES) { g_cnt[i] = 0; g_cur[i] = 0; }
    }

    // stage W transposed
    for (int i = tid; i < IN_F * OUT_F; i += 256) {
        int j = i >> 7;
        int k = i & 127;
        Wt[k][j] = W[i];
    }
    __syncthreads();

    int rows[4];
    #pragma unroll
    for (int i = 0; i < 4; i++) {
        int r = row_base + i;
        rows[i] = (r < N_NODES) ? r : (N_NODES - 1);
    }

    const float4* h4 = (const float4*)h;    // row stride = 32 float4

    float4 acc[4];
    #pragma unroll
    for (int i = 0; i < 4; i++) acc[i] = make_float4(0.f, 0.f, 0.f, 0.f);

    #pragma unroll 4
    for (int k4 = 0; k4 < IN_F / 4; k4++) {
        float4 wv0 = *(const float4*)&Wt[k4 * 4 + 0][col0];
        float4 wv1 = *(const float4*)&Wt[k4 * 4 + 1][col0];
        float4 wv2 = *(const float4*)&Wt[k4 * 4 + 2][col0];
        float4 wv3 = *(const float4*)&Wt[k4 * 4 + 3][col0];

        #pragma unroll
        for (int i = 0; i < 4; i++) {
            float4 hv = h4[(size_t)rows[i] * (IN_F / 4) + k4];
            acc[i].x = fmaf(hv.x, wv0.x, acc[i].x);
            acc[i].y = fmaf(hv.x, wv0.y, acc[i].y);
            acc[i].z = fmaf(hv.x, wv0.z, acc[i].z);
            acc[i].w = fmaf(hv.x, wv0.w, acc[i].w);
            acc[i].x = fmaf(hv.y, wv1.x, acc[i].x);
            acc[i].y = fmaf(hv.y, wv1.y, acc[i].y);
            acc[i].z = fmaf(hv.y, wv1.z, acc[i].z);
            acc[i].w = fmaf(hv.y, wv1.w, acc[i].w);
            acc[i].x = fmaf(hv.z, wv2.x, acc[i].x);
            acc[i].y = fmaf(hv.z, wv2.y, acc[i].y);
            acc[i].z = fmaf(hv.z, wv2.z, acc[i].z);
            acc[i].w = fmaf(hv.z, wv2.w, acc[i].w);
            acc[i].x = fmaf(hv.w, wv3.x, acc[i].x);
            acc[i].y = fmaf(hv.w, wv3.y, acc[i].y);
            acc[i].z = fmaf(hv.w, wv3.z, acc[i].z);
            acc[i].w = fmaf(hv.w, wv3.w, acc[i].w);
        }
    }

    const float4 al4 = *(const float4*)&a[col0];
    const float4 ar4 = *(const float4*)&a[OUT_F + col0];

    #pragma unroll
    for (int i = 0; i < 4; i++) {
        int r = row_base + i;
        bool ok = (r < N_NODES);
        if (ok)
            *(float4*)&g_z[(size_t)r * OUT_F + col0] = acc[i];

        float pel = acc[i].x * al4.x + acc[i].y * al4.y
                  + acc[i].z * al4.z + acc[i].w * al4.w;
        float per = acc[i].x * ar4.x + acc[i].y * ar4.y
                  + acc[i].z * ar4.z + acc[i].w * ar4.w;
        #pragma unroll
        for (int o = 4; o > 0; o >>= 1) {
            pel += __shfl_xor_sync(0xffffffffu, pel, o);
            per += __shfl_xor_sync(0xffffffffu, per, o);
        }
        if (ok && (tid & 7) == 0) {
            g_el[r] = pel;
            g_er[r] = per;
        }
    }
}

// ---------------------------------------------------------------------------
// A: histogram of dst
// ---------------------------------------------------------------------------
__global__ __launch_bounds__(256) void k_hist(const int* __restrict__ dst)
{
    int e = blockIdx.x * 256 + threadIdx.x;
    if (e < N_EDGES) atomicAdd(&g_cnt[dst[e]], 1);
}

// ---------------------------------------------------------------------------
// B1: per-chunk exclusive scan of g_cnt -> g_off (local), block sum -> g_bsum
// ---------------------------------------------------------------------------
__global__ __launch_bounds__(SCAN_CHUNK) void k_scan_local()
{
    __shared__ int s[SCAN_CHUNK];
    int t = threadIdx.x;
    int i = blockIdx.x * SCAN_CHUNK + t;
    int c = (i < N_NODES) ? g_cnt[i] : 0;
    s[t] = c;
    __syncthreads();
    // Hillis-Steele inclusive scan
    #pragma unroll
    for (int off = 1; off < SCAN_CHUNK; off <<= 1) {
        int v = (t >= off) ? s[t - off] : 0;
        __syncthreads();
        s[t] += v;
        __syncthreads();
    }
    if (i < N_NODES) g_off[i] = s[t] - c;        // exclusive
    if (t == SCAN_CHUNK - 1) g_bsum[blockIdx.x] = s[t];
}

// ---------------------------------------------------------------------------
// B2: exclusive scan of the 98 block sums (tiny, shared-mem serial)
// ---------------------------------------------------------------------------
__global__ __launch_bounds__(128) void k_scan_bsums()
{
    __shared__ int s[SCAN_BLOCKS];
    int t = threadIdx.x;
    if (t < SCAN_BLOCKS) s[t] = g_bsum[t];
    __syncthreads();
    if (t == 0) {
        int run = 0;
        for (int b = 0; b < SCAN_BLOCKS; b++) {
            int v = s[b];
            s[b] = run;
            run += v;
        }
    }
    __syncthreads();
    if (t < SCAN_BLOCKS) g_bsum[t] = s[t];
}

// ---------------------------------------------------------------------------
// B3: add block offsets
// ---------------------------------------------------------------------------
__global__ __launch_bounds__(SCAN_CHUNK) void k_scan_add()
{
    int i = blockIdx.x * SCAN_CHUNK + threadIdx.x;
    if (i < N_NODES) g_off[i] += g_bsum[blockIdx.x];
}

// ---------------------------------------------------------------------------
// C: per-edge ex = exp(leaky_relu(el[src]+er[dst])); scatter (src, ex)
//    into dst-sorted CSR order. (max-shift dropped: cancels in alpha.)
// ---------------------------------------------------------------------------
__global__ __launch_bounds__(256) void k_scatter(
    const int* __restrict__ src, const int* __restrict__ dst)
{
    int e = blockIdx.x * 256 + threadIdx.x;
    if (e >= N_EDGES) return;
    int s = src[e];
    int d = dst[e];
    float v = g_el[s] + g_er[d];
    v = (v > 0.0f) ? v : NEG_SLOPE * v;
    float ex = __expf(v);
    int pos = g_off[d] + atomicAdd(&g_cur[d], 1);
    g_srcex[pos] = make_int2(s, __float_as_int(ex));
}

// ---------------------------------------------------------------------------
// D: one warp per node: out[n] = (sum_e ex_e * z[src_e]) / (sum_e ex_e)
// 8 lanes per edge (float4 each), 4 edges in parallel per warp.
// Writes every out element -> no zero-init, no float atomics anywhere.
// ---------------------------------------------------------------------------
__global__ __launch_bounds__(256) void k_aggregate(float* __restrict__ out)
{
    int node = blockIdx.x * 8 + (threadIdx.x >> 5);
    if (node >= N_NODES) return;
    int lane = threadIdx.x & 31;
    int seg  = lane & 7;      // float4 index within row
    int grp  = lane >> 3;     // 0..3: which edge of a 4-edge batch

    int start = g_off[node];
    int cnt   = g_cnt[node];

    float4 acc = make_float4(0.f, 0.f, 0.f, 0.f);
    float exsum = 0.0f;

    for (int j = grp; j < cnt; j += 4) {
        int2 se = g_srcex[start + j];            // broadcast within group
        int s = se.x;
        float ex = __int_as_float(se.y);
        float4 zv = ((const float4*)(g_z + (size_t)s * OUT_F))[seg];
        acc.x = fmaf(ex, zv.x, acc.x);
        acc.y = fmaf(ex, zv.y, acc.y);
        acc.z = fmaf(ex, zv.z, acc.z);
        acc.w = fmaf(ex, zv.w, acc.w);
        exsum += ex;
    }

    // reduce across the 4 groups (lanes differing in bits 3,4)
    #pragma unroll
    for (int o = 8; o <= 16; o <<= 1) {
        acc.x += __shfl_xor_sync(0xffffffffu, acc.x, o);
        acc.y += __shfl_xor_sync(0xffffffffu, acc.y, o);
        acc.z += __shfl_xor_sync(0xffffffffu, acc.z, o);
        acc.w += __shfl_xor_sync(0xffffffffu, acc.w, o);
        exsum += __shfl_xor_sync(0xffffffffu, exsum, o);
    }

    float inv = 1.0f / fmaxf(exsum, 1e-16f);
    if (grp == 0) {
        float4 r = make_float4(acc.x * inv, acc.y * inv, acc.z * inv, acc.w * inv);
        ((float4*)(out + (size_t)node * OUT_F))[seg] = r;
    }
}

// ---------------------------------------------------------------------------
extern "C" void kernel_launch(void* const* d_in, const int* in_sizes, int n_in,
                              void* d_out, int out_size)
{
    const float* h   = (const float*)d_in[0];
    const float* W   = (const float*)d_in[1];
    const float* a   = (const float*)d_in[2];
    const int*   src = (const int*)d_in[3];
    const int*   dst = (const int*)d_in[4];
    float* out = (float*)d_out;

    (void)in_sizes; (void)n_in; (void)out_size;

    k_gemm<<<K1_BLOCKS, 256>>>(h, W, a);                     // 782 blocks
    k_hist<<<(N_EDGES + 255) / 256, 256>>>(dst);             // 6250
    k_scan_local<<<SCAN_BLOCKS, SCAN_CHUNK>>>();             // 98
    k_scan_bsums<<<1, 128>>>();                              // 1
    k_scan_add<<<SCAN_BLOCKS, SCAN_CHUNK>>>();               // 98
    k_scatter<<<(N_EDGES + 255) / 256, 256>>>(src, dst);     // 6250
    k_aggregate<<<(N_NODES + 7) / 8, 256>>>(out);            // 12500
}